// round 13
// baseline (speedup 1.0000x reference)
#include <cuda_runtime.h>
#include <math.h>

#define NB 8
#define NG 512
#define NT 1024
#define NK 5
#define NC 3

#define TPB 96                 // 32 targets x 3 channels
#define TBLK 32                // targets per block
#define PADG (NG + 1)          // padded row stride (bank-conflict-free)

__device__ __forceinline__ float ex2f(float x) {
    float y;
    asm("ex2.approx.ftz.f32 %0, %1;" : "=f"(y) : "f"(x));
    return y;
}

__global__ __launch_bounds__(TPB)
void fused_kernel(const float* __restrict__ x_grid,
                  const float* __restrict__ h_grid,
                  const float* __restrict__ target_x,
                  const float* __restrict__ sigma,
                  const float* __restrict__ g_w,
                  const float* __restrict__ g_b,
                  float* __restrict__ out)
{
    __shared__ __align__(16) float2 sA[NC][PADG];     // {2x', -x'^2}
    __shared__ __align__(16) float  shm[NC][PADG];    // hsum
    __shared__ __align__(16) float  raw[256 * NK * NC]; // 3840 floats (bounce buf)
    __shared__ float s_r[NC];
    __shared__ int   s_uni;

    const int tid  = threadIdx.x;
    const int warp = tid >> 5;
    const int lane = tid & 31;
    const int b    = blockIdx.y;

    const float* xg = x_grid + b * NG * NC;
    const float* hg = h_grid + b * NG * NK * NC;

    // ---- P0: warp0 coeffs (lane-parallel) || warps 1-2 load raw x ----
    if (warp == 0) {
        float sv = 1.0f;
        if (lane < NK * NC) sv = __expf(sigma[lane]) + 1e-6f;
        float s0 = __shfl_sync(0xffffffffu, sv, lane % NC);
        bool ok  = (lane < NK * NC) ? (sv == s0) : true;
        unsigned m = __ballot_sync(0xffffffffu, ok);
        if (lane == 0) s_uni = (m == 0xffffffffu);
        if (lane < NC) s_r[lane] = 0.84932180028802f / sv;  // sqrt(0.5*log2e)/s
    } else {
        // x: 1536 floats = 384 float4, 64 threads x 6
        const float4* xg4 = (const float4*)xg;
        const int i = tid - 32;
        #pragma unroll
        for (int j = 0; j < 6; j++)
            ((float4*)raw)[i + j * 64] = xg4[i + j * 64];
    }
    __syncthreads();

    // ---- P1: transform x -> sA (1536 tasks, 16 per thread) ----
    {
        const float rr0 = s_r[0], rr1 = s_r[1], rr2 = s_r[2];
        #pragma unroll
        for (int j = 0; j < 16; j++) {
            const int u = tid + j * TPB;
            const int g = u / NC, c = u - g * NC;
            const float rc = (c == 0) ? rr0 : (c == 1) ? rr1 : rr2;
            const float v = raw[u] * rc;
            sA[c][g] = make_float2(2.0f * v, -v * v);
        }
    }
    __syncthreads();

    // ---- P2..P5: h fold in two 256-row sections ----
    float gw[NK];
    #pragma unroll
    for (int k = 0; k < NK; k++) gw[k] = g_w[k];

    #pragma unroll
    for (int sec = 0; sec < 2; sec++) {
        // load section: 3840 floats = 960 float4, 10 per thread
        const float4* hg4 = (const float4*)(hg + sec * 256 * NK * NC);
        #pragma unroll
        for (int j = 0; j < 10; j++)
            ((float4*)raw)[tid + j * TPB] = hg4[tid + j * TPB];
        __syncthreads();

        // fold: rows tid, tid+96, (tid+192 if <256); stride-15 LDS conflict-free
        for (int j = tid; j < 256; j += TPB) {
            const float* hp = raw + j * (NK * NC);
            float h0 = 0.f, h1 = 0.f, h2 = 0.f;
            #pragma unroll
            for (int k = 0; k < NK; k++) {
                h0 += gw[k] * hp[k * NC + 0];
                h1 += gw[k] * hp[k * NC + 1];
                h2 += gw[k] * hp[k * NC + 2];
            }
            const int row = sec * 256 + j;
            shm[0][row] = h0; shm[1][row] = h1; shm[2][row] = h2;
        }
        __syncthreads();
    }

    // ---- per-thread target ----
    const int tl  = tid / NC;            // 0..31
    const int c   = tid - tl * NC;       // 0..2
    const int t   = blockIdx.x * TBLK + tl;
    const int oidx = (b * NT + t) * NC + c;
    const float tr = target_x[oidx];     // coalesced
    const float bb = g_b[0];

    if (s_uni) {
        // ======== FAST PATH: 512-iter loop on smem ========
        const float tpr = tr * s_r[c];
        const float2* Ac = sA[c];
        const float*  Hc = shm[c];

        float a0 = 0.f, a1 = 0.f, a2s = 0.f, a3 = 0.f;
        #pragma unroll 2
        for (int g = 0; g < NG; g += 4) {
            const float2 q0 = Ac[g + 0]; const float h0 = Hc[g + 0];
            const float2 q1 = Ac[g + 1]; const float h1 = Hc[g + 1];
            const float2 q2 = Ac[g + 2]; const float h2 = Hc[g + 2];
            const float2 q3 = Ac[g + 3]; const float h3 = Hc[g + 3];
            a0 += h0 * ex2f(fmaf(q0.x, tpr, q0.y));
            a1 += h1 * ex2f(fmaf(q1.x, tpr, q1.y));
            a2s += h2 * ex2f(fmaf(q2.x, tpr, q2.y));
            a3 += h3 * ex2f(fmaf(q3.x, tpr, q3.y));
        }
        const float sum = (a0 + a1) + (a2s + a3);
        out[oidx] = fmaf(sum, ex2f(-tpr * tpr), bb);
    } else {
        // ======== GENERAL PATH (cold): per-(k,c) scales, direct loads ========
        float a2c[NK];
        #pragma unroll
        for (int k = 0; k < NK; k++) {
            float s   = __expf(sigma[k * NC + c]) + 1e-6f;
            float inv = 1.0f / s;
            a2c[k]    = -0.5f * 1.4426950408889634f * inv * inv;
        }
        float acc = 0.f;
        for (int g = 0; g < NG; g++) {
            const float x = __ldg(&xg[g * NC + c]);
            const float d = x - tr;
            const float u = d * d;
            const float* hp = hg + g * NK * NC + c;
            #pragma unroll
            for (int k = 0; k < NK; k++)
                acc += gw[k] * __ldg(&hp[k * NC]) * ex2f(a2c[k] * u);
        }
        out[oidx] = acc + bb;
    }
}

extern "C" void kernel_launch(void* const* d_in, const int* in_sizes, int n_in,
                              void* d_out, int out_size)
{
    const float* x_grid   = (const float*)d_in[0];  // (8, 512, 3)
    const float* h_grid   = (const float*)d_in[1];  // (8, 512, 5, 3)
    const float* target_x = (const float*)d_in[2];  // (8, 1024, 3)
    const float* sigma    = (const float*)d_in[3];  // (5, 3)
    const float* g_w      = (const float*)d_in[4];  // (1, 5)
    const float* g_b      = (const float*)d_in[5];  // (1,)
    float* out = (float*)d_out;                     // (8, 1024, 3)

    dim3 grid(NT / TBLK, NB);   // 32 x 8 = 256 blocks of 96 threads
    fused_kernel<<<grid, TPB>>>(x_grid, h_grid, target_x, sigma, g_w, g_b, out);
}

// round 14
// speedup vs baseline: 1.1896x; 1.1896x over previous
#include <cuda_runtime.h>
#include <math.h>

#define NB 8
#define NG 512
#define NT 1024
#define NK 5
#define NC 3

#define PREP_TPB 256
#define MAIN_TPB 128
#define TGRP (NT / MAIN_TPB)     // 8 target-groups
#define NCHUNK 16
#define CHUNK_G (NG / NCHUNK)    // 32 grid rows per chunk

// device scratch (allocation-free per harness rules)
__device__ float4 d_p1[NB * NG];   // {2x0', -x0'^2, 2x1', -x1'^2}
__device__ float4 d_p2[NB * NG];   // {2x2', -x2'^2, h0, h1}
__device__ float  d_p3[NB * NG];   // h2

__device__ __forceinline__ float ex2f(float x) {
    float y;
    asm("ex2.approx.ftz.f32 %0, %1;" : "=f"(y) : "f"(x));
    return y;
}

// ---------------- prep: 16 fold blocks + 24 out-init blocks ----------------
__global__ __launch_bounds__(PREP_TPB)
void prep_kernel(const float* __restrict__ x_grid,
                 const float* __restrict__ h_grid,
                 const float* __restrict__ sigma,
                 const float* __restrict__ g_w,
                 const float* __restrict__ g_b,
                 float4* __restrict__ out4)
{
    __shared__ __align__(16) float sh[256 * NK * NC];   // 3840 floats = 15KB

    const int tid = threadIdx.x;
    const int blk = blockIdx.x;

    if (blk < 16) {
        // coefficients (tiny, every thread)
        float a2[NK][NC];
        #pragma unroll
        for (int k = 0; k < NK; k++)
            #pragma unroll
            for (int c = 0; c < NC; c++) {
                float s   = __expf(sigma[k * NC + c]) + 1e-6f;
                float inv = 1.0f / s;
                a2[k][c]  = -0.5f * 1.4426950408889634f * inv * inv;
            }
        bool uni = true;
        #pragma unroll
        for (int k = 1; k < NK; k++)
            #pragma unroll
            for (int c = 0; c < NC; c++)
                uni = uni && (a2[k][c] == a2[0][c]);

        const float r0 = uni ? sqrtf(-a2[0][0]) : 1.0f;
        const float r1 = uni ? sqrtf(-a2[0][1]) : 1.0f;
        const float r2 = uni ? sqrtf(-a2[0][2]) : 1.0f;

        // ---- fold rows rbase .. rbase+255 ----
        const int rbase = blk * 256;
        const float4* hg4 = (const float4*)(h_grid) + rbase * (NK * NC) / 4;
        #pragma unroll
        for (int i = 0; i < 4; i++) {
            int idx = tid + i * PREP_TPB;
            if (idx < 960) ((float4*)sh)[idx] = hg4[idx];
        }
        __syncthreads();

        const int row = rbase + tid;
        const float* hp = sh + tid * (NK * NC);   // stride 15: conflict-free
        float gw[NK];
        #pragma unroll
        for (int k = 0; k < NK; k++) gw[k] = g_w[k];
        float h0 = 0.f, h1 = 0.f, h2 = 0.f;
        #pragma unroll
        for (int k = 0; k < NK; k++) {
            h0 += gw[k] * hp[k * NC + 0];
            h1 += gw[k] * hp[k * NC + 1];
            h2 += gw[k] * hp[k * NC + 2];
        }
        const float* xp = x_grid + row * NC;
        const float sx0 = xp[0] * r0, sx1 = xp[1] * r1, sx2 = xp[2] * r2;
        d_p1[row] = make_float4(2.f * sx0, -sx0 * sx0, 2.f * sx1, -sx1 * sx1);
        d_p2[row] = make_float4(2.f * sx2, -sx2 * sx2, h0, h1);
        d_p3[row] = h2;
    } else {
        // ---- out := bias (24 blocks x 256 = 6144 float4) ----
        const int i = (blk - 16) * PREP_TPB + tid;
        const float bb = g_b[0];
        out4[i] = make_float4(bb, bb, bb, bb);
    }

    // allow dependent (main) grid to launch early; its griddepcontrol.wait
    // still guarantees visibility of all our stores.
    asm volatile("griddepcontrol.launch_dependents;");
}

// ---------------- main: thread-per-target, 32-row g-chunk, PDL ----------------
__global__ __launch_bounds__(MAIN_TPB)
void main_kernel(const float* __restrict__ x_grid,
                 const float* __restrict__ h_grid,
                 const float* __restrict__ target_x,
                 const float* __restrict__ sigma,
                 const float* __restrict__ g_w,
                 float* __restrict__ out)
{
    __shared__ __align__(16) float4 s1[CHUNK_G];
    __shared__ __align__(16) float4 s2[CHUNK_G];
    __shared__ __align__(16) float  s3[CHUNK_G];
    __shared__ float s_r[NC];
    __shared__ int   s_uni;

    const int tid    = threadIdx.x;
    const int warp   = tid >> 5;
    const int lane   = tid & 31;
    const int tgroup = blockIdx.x;
    const int chunk  = blockIdx.y;
    const int b      = blockIdx.z;
    const int g0     = chunk * CHUNK_G;
    const int gbase  = b * NG + g0;

    // ======== PRE-WAIT PROLOGUE (independent of prep) ========
    if (warp == 0) {
        float sv = 1.0f;
        if (lane < NK * NC) sv = __expf(sigma[lane]) + 1e-6f;   // lane = k*3+c
        float s0 = __shfl_sync(0xffffffffu, sv, lane % NC);
        bool ok  = (lane < NK * NC) ? (sv == s0) : true;
        unsigned m = __ballot_sync(0xffffffffu, ok);
        if (lane == 0) s_uni = (m == 0xffffffffu);
        if (lane < NC) s_r[lane] = 0.84932180028802f / sv;   // sqrt(0.5*log2e)/s
    }

    const int t     = tgroup * MAIN_TPB + tid;
    const int obase = (b * NT + t) * NC;
    const float tr0 = target_x[obase + 0];
    const float tr1 = target_x[obase + 1];
    const float tr2 = target_x[obase + 2];

    __syncthreads();
    const int uni = s_uni;
    const float tp0 = tr0 * s_r[0];
    const float tp1 = tr1 * s_r[1];
    const float tp2 = tr2 * s_r[2];

    // ======== WAIT for prep's memory (out-init + d_p*) ========
    asm volatile("griddepcontrol.wait;" ::: "memory");

    float acc0 = 0.f, acc1 = 0.f, acc2 = 0.f;

    if (uni) {
        // stage: 72 threads, one LDG.128 each
        if (tid < CHUNK_G)                 s1[tid]           = d_p1[gbase + tid];
        else if (tid < 2 * CHUNK_G)        s2[tid - CHUNK_G] = d_p2[gbase + tid - CHUNK_G];
        else if (tid < 2 * CHUNK_G + CHUNK_G / 4)
            ((float4*)s3)[tid - 2 * CHUNK_G] = ((const float4*)(d_p3 + gbase))[tid - 2 * CHUNK_G];
        __syncthreads();

        #pragma unroll
        for (int gi = 0; gi < CHUNK_G; gi++) {
            const float4 A = s1[gi];   // {2x0, -x0^2, 2x1, -x1^2}
            const float4 B = s2[gi];   // {2x2, -x2^2, h0, h1}
            const float  h2 = s3[gi];
            acc0 += B.z * ex2f(fmaf(A.x, tp0, A.y));
            acc1 += B.w * ex2f(fmaf(A.z, tp1, A.w));
            acc2 += h2  * ex2f(fmaf(B.x, tp2, B.y));
        }
        acc0 *= ex2f(-tp0 * tp0);
        acc1 *= ex2f(-tp1 * tp1);
        acc2 *= ex2f(-tp2 * tp2);
    } else {
        // cold general path: per-(k,c) scales, direct loads (raw targets)
        float a2[NK][NC];
        #pragma unroll
        for (int k = 0; k < NK; k++)
            #pragma unroll
            for (int c = 0; c < NC; c++) {
                float s   = __expf(sigma[k * NC + c]) + 1e-6f;
                float inv = 1.0f / s;
                a2[k][c]  = -0.5f * 1.4426950408889634f * inv * inv;
            }
        float gw[NK];
        #pragma unroll
        for (int k = 0; k < NK; k++) gw[k] = __ldg(&g_w[k]);

        const float* xg = x_grid + gbase * NC;
        const float* hg = h_grid + gbase * NK * NC;
        for (int gi = 0; gi < CHUNK_G; gi++) {
            const float* xp = xg + gi * NC;
            const float x0 = __ldg(&xp[0]), x1 = __ldg(&xp[1]), x2 = __ldg(&xp[2]);
            const float u0 = (x0 - tr0) * (x0 - tr0);
            const float u1 = (x1 - tr1) * (x1 - tr1);
            const float u2 = (x2 - tr2) * (x2 - tr2);
            const float* hp = hg + gi * NK * NC;
            #pragma unroll
            for (int k = 0; k < NK; k++) {
                acc0 += gw[k] * __ldg(&hp[k * NC + 0]) * ex2f(a2[k][0] * u0);
                acc1 += gw[k] * __ldg(&hp[k * NC + 1]) * ex2f(a2[k][1] * u1);
                acc2 += gw[k] * __ldg(&hp[k * NC + 2]) * ex2f(a2[k][2] * u2);
            }
        }
    }

    // fire-and-forget REDs into bias-initialized out
    atomicAdd(&out[obase + 0], acc0);
    atomicAdd(&out[obase + 1], acc1);
    atomicAdd(&out[obase + 2], acc2);
}

extern "C" void kernel_launch(void* const* d_in, const int* in_sizes, int n_in,
                              void* d_out, int out_size)
{
    const float* x_grid   = (const float*)d_in[0];  // (8, 512, 3)
    const float* h_grid   = (const float*)d_in[1];  // (8, 512, 5, 3)
    const float* target_x = (const float*)d_in[2];  // (8, 1024, 3)
    const float* sigma    = (const float*)d_in[3];  // (5, 3)
    const float* g_w      = (const float*)d_in[4];  // (1, 5)
    const float* g_b      = (const float*)d_in[5];  // (1,)
    float* out = (float*)d_out;                     // (8, 1024, 3)

    // prep: 16 fold blocks + 24 out-init blocks
    prep_kernel<<<40, PREP_TPB>>>(x_grid, h_grid, sigma, g_w, g_b, (float4*)out);

    // main with Programmatic Dependent Launch: overlaps prep
    cudaLaunchConfig_t cfg = {};
    cfg.gridDim  = dim3(TGRP, NCHUNK, NB);   // 8 x 16 x 8 = 1024 blocks
    cfg.blockDim = dim3(MAIN_TPB, 1, 1);
    cudaLaunchAttribute attr[1];
    attr[0].id = cudaLaunchAttributeProgrammaticStreamSerialization;
    attr[0].val.programmaticStreamSerializationAllowed = 1;
    cfg.attrs = attr;
    cfg.numAttrs = 1;
    cudaLaunchKernelEx(&cfg, main_kernel, x_grid, h_grid, target_x, sigma, g_w, out);
}